// round 9
// baseline (speedup 1.0000x reference)
#include <cuda_runtime.h>
#include <cuda_fp16.h>
#include <mma.h>
#include <cstdint>
#include <cstddef>
using namespace nvcuda;

#define NNODES 55296
#define NEDGES 221184
#define N32 (NNODES * 32)

// ------------------------- device scratch -----------------------------------
__device__ __align__(256) float g_h[2 * N32];
__device__ __align__(256) float g_agg[2 * N32];
__device__ __align__(256) __half g_tA[(size_t)NEDGES * 32];   // t hi fp16
__device__ __align__(256) __half g_Bt[32 * 1024];             // B' permuted
__device__ __align__(256) float g_biasp[1024];                // eb2 permuted
__device__ __align__(256) __half g_We[(size_t)NEDGES * 1024]; // [e][j] j=(q,o,hl)

__device__ __forceinline__ float fsig(float x) { return 1.f / (1.f + __expf(-x)); }
__device__ __forceinline__ uint64_t mkpol_ef() {
    uint64_t p;
    asm("createpolicy.fractional.L2::evict_first.b64 %0;" : "=l"(p));
    return p;
}
__device__ __forceinline__ uint4 ld_ef(const void* gp, uint64_t pol) {
    uint4 v;
    asm volatile("ld.global.nc.L2::cache_hint.v4.u32 {%0,%1,%2,%3}, [%4], %5;"
                 : "=r"(v.x), "=r"(v.y), "=r"(v.z), "=r"(v.w)
                 : "l"(gp), "l"(pol));
    return v;
}
__device__ __forceinline__ void st_ef(void* gp, uint4 v, uint64_t pol) {
    asm volatile("st.global.L2::cache_hint.v4.b32 [%0], {%1,%2,%3,%4}, %5;"
                 :: "l"(gp), "r"(v.x), "r"(v.y), "r"(v.z), "r"(v.w), "l"(pol)
                 : "memory");
}

// ---- launch 0: B' build [32][1024] + permuted bias --------------------------
__global__ void preB_kernel(const float* __restrict__ ew2,
                            const float* __restrict__ eb2) {
    int b = blockIdx.x, tid = threadIdx.x;
    if (b < 128) {
        int i = b * 256 + tid;
        int k = i >> 10, j = i & 1023;
        int h = ((j >> 8) << 3) + (j & 7), o = (j >> 3) & 31;
        g_Bt[i] = __float2half(ew2[k * 1024 + h * 32 + o]);
    } else {
#pragma unroll
        for (int u = 0; u < 4; u++) {
            int j = tid * 4 + u;
            int h = ((j >> 8) << 3) + (j & 7), o = (j >> 3) & 31;
            g_biasp[j] = eb2[h * 32 + o];
        }
    }
}

// ---- launch 1: t = relu(rel@ew1+eb1) -> fp16 --------------------------------
__global__ void preT_kernel(const float4* __restrict__ rel4,
                            const float* __restrict__ ew1,
                            const float* __restrict__ eb1) {
    int g = blockIdx.x * 256 + threadIdx.x;
    int e = g >> 5, k = g & 31;
    float4 r = rel4[e];
    float v = eb1[k] + r.x * ew1[k] + r.y * ew1[32 + k] + r.z * ew1[64 + k] +
              r.w * ew1[96 + k];
    g_tA[(size_t)e * 32 + k] = __float2half(fmaxf(v, 0.f));
}

// ---- launch 2: h0 projection + zero g_agg (8 nodes per warp) ----------------
__global__ __launch_bounds__(256) void h0z_kernel(const float* __restrict__ x,
                                                  const float* __restrict__ pw1,
                                                  const float* __restrict__ pb1,
                                                  const float* __restrict__ pw2,
                                                  const float* __restrict__ pb2) {
    __shared__ float sW1[1024], sW2[1024];
    int tid = threadIdx.x, lane = tid & 31;
#pragma unroll
    for (int i = 0; i < 8; i++)
        g_agg[blockIdx.x * 256 + tid + i * 442368] = 0.f;
    for (int i = tid; i < 1024; i += 256) { sW1[i] = pw1[i]; sW2[i] = pw2[i]; }
    __syncthreads();
    int wbase = blockIdx.x * 8 + (tid >> 5);
#pragma unroll 1
    for (int it = 0; it < 8; it++) {
        int gw = wbase + it * 13824;
        float xr = x[(size_t)gw * 32 + lane];
        float t1 = pb1[lane];
#pragma unroll
        for (int h = 0; h < 32; h++)
            t1 = fmaf(__shfl_sync(0xffffffffu, xr, h), sW1[h * 32 + lane], t1);
        t1 = fmaxf(t1, 0.f);
        float o = pb2[lane];
#pragma unroll
        for (int h = 0; h < 32; h++)
            o = fmaf(__shfl_sync(0xffffffffu, t1, h), sW2[h * 32 + lane], o);
        g_h[(size_t)gw * 32 + lane] = o;
    }
}

// ---- launch 3 (PROFILED): We GEMM, B fragments register-resident ------------
#define SA 0                 // 128*40*2  = 10240
#define SB 10240             // 32*1032*2 = 66048
#define SBIAS 76288          // 4096
#define SC 80384             // 8*16*68*4 = 34816
#define STOT 115200

__global__ __launch_bounds__(256) void we_wmma_kernel() {
    extern __shared__ char sm[];
    __half* sA = (__half*)(sm + SA);
    __half* sB = (__half*)(sm + SB);
    float* sBias = (float*)(sm + SBIAS);
    float* sC = (float*)(sm + SC);
    int tid = threadIdx.x, wid = tid >> 5, lane = tid & 31;
    uint64_t pol = mkpol_ef();

    // A tile: 128 edges x 32 halves, pad stride 40
    const uint4* ga = (const uint4*)(g_tA + (size_t)blockIdx.x * 128 * 32);
#pragma unroll
    for (int r = 0; r < 2; r++) {
        int i = tid + r * 256, row = i >> 2, c = i & 3;
        *(uint4*)(sA + row * 40 + c * 8) = ga[i];
    }
    // B' full: 32 x 1024 halves, pad stride 1032
    const uint4* gb = (const uint4*)(const void*)g_Bt;
#pragma unroll
    for (int r = 0; r < 16; r++) {
        int i = tid + r * 256, row = i >> 7, c = i & 127;
        *(uint4*)(sB + row * 1032 + c * 8) = gb[i];
    }
#pragma unroll
    for (int r = 0; r < 4; r++) sBias[tid + r * 256] = g_biasp[tid + r * 256];
    __syncthreads();

    // warp owns cols [wid*128, wid*128+128): 16 B fragments, loaded ONCE
    wmma::fragment<wmma::matrix_b, 16, 16, 16, __half, wmma::row_major> bf[2][8];
#pragma unroll
    for (int k = 0; k < 2; k++)
#pragma unroll
        for (int f = 0; f < 8; f++)
            wmma::load_matrix_sync(bf[k][f], sB + (k * 16) * 1032 + wid * 128 + f * 16,
                                   1032);

    float* sCw = sC + wid * 16 * 68;
    const int rsub = lane >> 3, ch = lane & 7;
#pragma unroll 1
    for (int m = 0; m < 8; m++) {
        wmma::fragment<wmma::matrix_a, 16, 16, 16, __half, wmma::row_major> a0, a1;
        wmma::load_matrix_sync(a0, sA + (m * 16) * 40, 40);
        wmma::load_matrix_sync(a1, sA + (m * 16) * 40 + 16, 40);
        wmma::fragment<wmma::accumulator, 16, 16, 16, float> acc[8];
#pragma unroll
        for (int f = 0; f < 8; f++) {
            wmma::fill_fragment(acc[f], 0.f);
            wmma::mma_sync(acc[f], a0, bf[0][f], acc[f]);
            wmma::mma_sync(acc[f], a1, bf[1][f], acc[f]);
        }
#pragma unroll 1
        for (int half = 0; half < 2; half++) {
            __syncwarp();
#pragma unroll
            for (int f = 0; f < 4; f++)
                wmma::store_matrix_sync(sCw + f * 16, acc[half * 4 + f], 68,
                                        wmma::mem_row_major);
            __syncwarp();
            const float* bp = sBias + wid * 128 + half * 64 + ch * 8;
#pragma unroll
            for (int p = 0; p < 4; p++) {
                int row = p * 4 + rsub;
                const float* rp = sCw + row * 68 + ch * 8;
                float4 v0 = *(const float4*)rp;
                float4 v1 = *(const float4*)(rp + 4);
                __half2 a = __floats2half2_rn(v0.x + bp[0], v0.y + bp[1]);
                __half2 b2 = __floats2half2_rn(v0.z + bp[2], v0.w + bp[3]);
                __half2 c2 = __floats2half2_rn(v1.x + bp[4], v1.y + bp[5]);
                __half2 d2 = __floats2half2_rn(v1.z + bp[6], v1.w + bp[7]);
                int e = blockIdx.x * 128 + m * 16 + row;
                uint4 pk = make_uint4(*(uint32_t*)&a, *(uint32_t*)&b2,
                                      *(uint32_t*)&c2, *(uint32_t*)&d2);
                st_ef((char*)(void*)g_We + (size_t)e * 2048 + wid * 256 +
                          half * 128 + ch * 16,
                      pk, pol);
            }
        }
    }
}

// ---- msg + scatter, 2 edges per warp (DRAM-bound, ~roofline) ----------------
__global__ __launch_bounds__(256) void msg_kernel(const int* __restrict__ src,
                                                  const int* __restrict__ dst) {
    __shared__ __align__(16) float ns[8][4][32];
    const int w = threadIdx.x >> 5, lane = threadIdx.x & 31;
    const int e0 = blockIdx.x * 16 + w * 2;
    uint64_t pol = mkpol_ef();
    int s0 = __ldg(&src[e0]), s1 = __ldg(&src[e0 + 1]);
    int d0 = __ldg(&dst[e0]), d1 = __ldg(&dst[e0 + 1]);
    ns[w][0][lane] = g_h[(size_t)s0 * 32 + lane];
    ns[w][1][lane] = g_h[N32 + (size_t)s0 * 32 + lane];
    ns[w][2][lane] = g_h[(size_t)s1 * 32 + lane];
    ns[w][3][lane] = g_h[N32 + (size_t)s1 * 32 + lane];
    uint4 q[8];
#pragma unroll
    for (int ee = 0; ee < 2; ee++)
#pragma unroll
        for (int qi = 0; qi < 4; qi++)
            q[ee * 4 + qi] = ld_ef((const char*)(const void*)g_We +
                                       (size_t)(e0 + ee) * 2048 + qi * 512 +
                                       lane * 16,
                                   pol);
    __syncwarp();
    float acc[4] = {0.f, 0.f, 0.f, 0.f};
#pragma unroll
    for (int ee = 0; ee < 2; ee++) {
#pragma unroll
        for (int qi = 0; qi < 4; qi++) {
            uint32_t w4[4] = {q[ee * 4 + qi].x, q[ee * 4 + qi].y,
                              q[ee * 4 + qi].z, q[ee * 4 + qi].w};
#pragma unroll
            for (int u = 0; u < 4; u++) {
                float2 wf = __half22float2(*(__half2*)&w4[u]);
                int h = qi * 8 + 2 * u;
                float2 p0 = *(const float2*)&ns[w][ee * 2][h];
                float2 p1 = *(const float2*)&ns[w][ee * 2 + 1][h];
                acc[ee * 2] += p0.x * wf.x + p0.y * wf.y;
                acc[ee * 2 + 1] += p1.x * wf.x + p1.y * wf.y;
            }
        }
    }
#pragma unroll
    for (int ee = 0; ee < 2; ee++) {
        int d = ee ? d1 : d0;
        float a0 = acc[ee * 2], a1 = acc[ee * 2 + 1];
        float u = __shfl_down_sync(0xffffffffu, a0, 1);
        float v = __shfl_up_sync(0xffffffffu, a1, 1);
        if (!(lane & 1))
            asm volatile("red.global.add.v2.f32 [%0], {%1,%2};"
                         :: "l"(&g_agg[(size_t)d * 32 + lane]), "f"(a0), "f"(u)
                         : "memory");
        else
            asm volatile("red.global.add.v2.f32 [%0], {%1,%2};"
                         :: "l"(&g_agg[N32 + (size_t)d * 32 + lane - 1]), "f"(v),
                            "f"(a1)
                         : "memory");
    }
}

// ---- relu + GRU: 8 nodes per warp, amortized weight staging -----------------
__global__ __launch_bounds__(256) void gru_kernel(const float* __restrict__ convb,
                                                  const float* __restrict__ wih,
                                                  const float* __restrict__ whh,
                                                  const float* __restrict__ bih,
                                                  const float* __restrict__ bhh,
                                                  float* __restrict__ outp) {
    __shared__ float sWih[3104], sWhh[3104];  // [h][j] stride 97
    int tid = threadIdx.x, lane = tid & 31;
    for (int i = tid; i < 3072; i += 256) {
        int j = i >> 5, h = i & 31;
        sWih[h * 97 + j] = wih[i];
        sWhh[h * 97 + j] = whh[i];
    }
    __syncthreads();
    int wbase = blockIdx.x * 8 + (tid >> 5);
#pragma unroll 1
    for (int it = 0; it < 8; it++) {
        int gw = wbase + it * 13824;
        size_t idx = (size_t)gw * 32 + lane;
        float node = fmaxf(g_agg[idx] + convb[lane], 0.f);
        g_agg[idx] = 0.f;
        float hid = g_h[idx];
        float gx0 = bih[lane], gx1 = bih[32 + lane], gx2 = bih[64 + lane];
        float gh0 = bhh[lane], gh1 = bhh[32 + lane], gh2 = bhh[64 + lane];
#pragma unroll
        for (int h = 0; h < 32; h++) {
            float nv = __shfl_sync(0xffffffffu, node, h);
            float hv = __shfl_sync(0xffffffffu, hid, h);
            const float* wi = &sWih[h * 97];
            const float* wh = &sWhh[h * 97];
            gx0 = fmaf(nv, wi[lane], gx0);
            gx1 = fmaf(nv, wi[32 + lane], gx1);
            gx2 = fmaf(nv, wi[64 + lane], gx2);
            gh0 = fmaf(hv, wh[lane], gh0);
            gh1 = fmaf(hv, wh[32 + lane], gh1);
            gh2 = fmaf(hv, wh[64 + lane], gh2);
        }
        float r = fsig(gx0 + gh0);
        float z = fsig(gx1 + gh1);
        float n = tanhf(gx2 + r * gh2);
        float hn = (1.f - z) * n + z * hid;
        g_h[idx] = hn;
        if (outp) outp[idx] = hn;
    }
}

// ------------------------- launch -------------------------------------------
extern "C" void kernel_launch(void* const* d_in, const int* in_sizes, int n_in,
                              void* d_out, int out_size) {
    const float* x     = (const float*)d_in[0];
    const float* rel   = (const float*)d_in[1];
    const float* pw1   = (const float*)d_in[2];
    const float* pb1   = (const float*)d_in[3];
    const float* pw2   = (const float*)d_in[4];
    const float* pb2   = (const float*)d_in[5];
    const float* ew1   = (const float*)d_in[6];
    const float* eb1   = (const float*)d_in[7];
    const float* ew2   = (const float*)d_in[8];
    const float* eb2   = (const float*)d_in[9];
    const float* convb = (const float*)d_in[10];
    const float* wih   = (const float*)d_in[11];
    const float* whh   = (const float*)d_in[12];
    const float* bih   = (const float*)d_in[13];
    const float* bhh   = (const float*)d_in[14];
    const int*   src   = (const int*)d_in[15];
    const int*   dst   = (const int*)d_in[16];
    float* out = (float*)d_out;

    cudaFuncSetAttribute(we_wmma_kernel,
                         cudaFuncAttributeMaxDynamicSharedMemorySize, STOT);
    preB_kernel<<<129, 256>>>(ew2, eb2);
    preT_kernel<<<(NEDGES * 32) / 256, 256>>>((const float4*)rel, ew1, eb1);
    h0z_kernel<<<1728, 256>>>(x, pw1, pb1, pw2, pb2);
    we_wmma_kernel<<<NEDGES / 128, 256, STOT>>>();
    for (int step = 0; step < 3; step++) {
        msg_kernel<<<NEDGES / 16, 256>>>(src, dst);
        gru_kernel<<<1728, 256>>>(convb, wih, whh, bih, bhh,
                                  step == 2 ? out : nullptr);
    }
}

// round 10
// speedup vs baseline: 1.2674x; 1.2674x over previous
#include <cuda_runtime.h>
#include <cuda_fp16.h>
#include <mma.h>
#include <cstdint>
#include <cstddef>
using namespace nvcuda;

#define NNODES 55296
#define NEDGES 221184
#define N32 (NNODES * 32)
#define NW 13824  // total warps in node-kernels (1728 blocks x 8)

// ------------------------- device scratch -----------------------------------
__device__ __align__(256) float g_h[2 * N32];
__device__ __align__(256) float g_agg[2 * N32];
__device__ __align__(256) __half g_tA[(size_t)NEDGES * 32];   // t hi fp16
__device__ __align__(256) __half g_Bt[32 * 1024];             // B' permuted
__device__ __align__(256) float g_biasp[1024];                // eb2 permuted
__device__ __align__(256) __half g_We[(size_t)NEDGES * 1024]; // [e][j] j=(q,o,hl)

__device__ __forceinline__ float frcp(float x) {
    float r;
    asm("rcp.approx.f32 %0, %1;" : "=f"(r) : "f"(x));
    return r;
}
__device__ __forceinline__ float fsig(float x) {
    return frcp(1.f + __expf(-x));
}
__device__ __forceinline__ float ftanh(float x) {
    return 1.f - 2.f * frcp(1.f + __expf(2.f * x));
}
__device__ __forceinline__ uint64_t mkpol_ef() {
    uint64_t p;
    asm("createpolicy.fractional.L2::evict_first.b64 %0;" : "=l"(p));
    return p;
}
__device__ __forceinline__ uint4 ld_ef(const void* gp, uint64_t pol) {
    uint4 v;
    asm volatile("ld.global.nc.L2::cache_hint.v4.u32 {%0,%1,%2,%3}, [%4], %5;"
                 : "=r"(v.x), "=r"(v.y), "=r"(v.z), "=r"(v.w)
                 : "l"(gp), "l"(pol));
    return v;
}
__device__ __forceinline__ void st_ef(void* gp, uint4 v, uint64_t pol) {
    asm volatile("st.global.L2::cache_hint.v4.b32 [%0], {%1,%2,%3,%4}, %5;"
                 :: "l"(gp), "r"(v.x), "r"(v.y), "r"(v.z), "r"(v.w), "l"(pol)
                 : "memory");
}

// ---- launch 0: fused pre: B' build + bias permute + t build + h0 + zero ----
__global__ __launch_bounds__(256) void pre_kernel(
    const float* __restrict__ ew2, const float* __restrict__ eb2,
    const float4* __restrict__ rel4, const float* __restrict__ ew1,
    const float* __restrict__ eb1, const float* __restrict__ x,
    const float* __restrict__ pw1, const float* __restrict__ pb1,
    const float* __restrict__ pw2, const float* __restrict__ pb2) {
    int b = blockIdx.x, tid = threadIdx.x;
    if (b < 128) {               // B' [32][1024]: col j = q*256+o*8+hl
        int i = b * 256 + tid;
        int k = i >> 10, j = i & 1023;
        int h = ((j >> 8) << 3) + (j & 7), o = (j >> 3) & 31;
        g_Bt[i] = __float2half(ew2[k * 1024 + h * 32 + o]);
    } else if (b == 128) {       // permuted bias
#pragma unroll
        for (int u = 0; u < 4; u++) {
            int j = tid * 4 + u;
            int h = ((j >> 8) << 3) + (j & 7), o = (j >> 3) & 31;
            g_biasp[j] = eb2[h * 32 + o];
        }
    } else if (b < 129 + 27648) {  // t = relu(rel@ew1+eb1) -> fp16
        int g = (b - 129) * 256 + tid;
        int e = g >> 5, k = g & 31;
        float4 r = rel4[e];
        float v = eb1[k] + r.x * ew1[k] + r.y * ew1[32 + k] +
                  r.z * ew1[64 + k] + r.w * ew1[96 + k];
        g_tA[(size_t)e * 32 + k] = __float2half(fmaxf(v, 0.f));
    } else {                     // h0 projection + zero g_agg (8 nodes/warp)
        int hb = b - 129 - 27648;  // 0..1727
        __shared__ float sW1[1024], sW2[1024];
        int lane = tid & 31;
#pragma unroll
        for (int i = 0; i < 8; i++)
            g_agg[hb * 256 + tid + i * 442368] = 0.f;
        for (int i = tid; i < 1024; i += 256) { sW1[i] = pw1[i]; sW2[i] = pw2[i]; }
        __syncthreads();
        int wbase = hb * 8 + (tid >> 5);
#pragma unroll 1
        for (int it = 0; it < 8; it++) {
            int gw = wbase + it * NW;
            float xr = x[(size_t)gw * 32 + lane];
            float t1 = pb1[lane];
#pragma unroll
            for (int h = 0; h < 32; h++)
                t1 = fmaf(__shfl_sync(0xffffffffu, xr, h), sW1[h * 32 + lane], t1);
            t1 = fmaxf(t1, 0.f);
            float o = pb2[lane];
#pragma unroll
            for (int h = 0; h < 32; h++)
                o = fmaf(__shfl_sync(0xffffffffu, t1, h), sW2[h * 32 + lane], o);
            g_h[(size_t)gw * 32 + lane] = o;
        }
    }
}

// ---- launch 1: We GEMM [128x32]@[32x1024] wmma (R8 version, measured 187us) -
#define SA 0                 // 128*40*2  = 10240
#define SB 10240             // 32*1032*2 = 66048
#define SC 76288             // 8*16*68*4 = 34816
#define SBIAS 111104         // 4096
#define STOT 115200

__global__ __launch_bounds__(256, 2) void we_wmma_kernel() {
    extern __shared__ char sm[];
    __half* sA = (__half*)(sm + SA);
    __half* sB = (__half*)(sm + SB);
    float* sC = (float*)(sm + SC);
    float* sBias = (float*)(sm + SBIAS);
    int tid = threadIdx.x, wid = tid >> 5, lane = tid & 31;
    uint64_t pol = mkpol_ef();

    // A tile: 128 edges x 32 halves, pad stride 40
    const uint4* ga = (const uint4*)(g_tA + (size_t)blockIdx.x * 128 * 32);
#pragma unroll
    for (int r = 0; r < 2; r++) {
        int i = tid + r * 256, row = i >> 2, c = i & 3;
        *(uint4*)(sA + row * 40 + c * 8) = ga[i];
    }
    // B' full: 32 x 1024 halves, pad stride 1032
    const uint4* gb = (const uint4*)(const void*)g_Bt;
#pragma unroll
    for (int r = 0; r < 16; r++) {
        int i = tid + r * 256, row = i >> 7, c = i & 127;
        *(uint4*)(sB + row * 1032 + c * 8) = gb[i];
    }
#pragma unroll
    for (int r = 0; r < 4; r++) sBias[tid + r * 256] = g_biasp[tid + r * 256];
    __syncthreads();

    float* sCw = sC + wid * 16 * 68;
    const int rsub = lane >> 3, ch = lane & 7;
    for (int nt = 0; nt < 16; nt++) {
        wmma::fragment<wmma::accumulator, 16, 16, 16, float> acc[4];
#pragma unroll
        for (int f = 0; f < 4; f++) wmma::fill_fragment(acc[f], 0.f);
#pragma unroll
        for (int k = 0; k < 2; k++) {
            wmma::fragment<wmma::matrix_a, 16, 16, 16, __half, wmma::row_major> af;
            wmma::load_matrix_sync(af, sA + (wid * 16) * 40 + k * 16, 40);
#pragma unroll
            for (int f = 0; f < 4; f++) {
                wmma::fragment<wmma::matrix_b, 16, 16, 16, __half, wmma::row_major> bf;
                wmma::load_matrix_sync(bf, sB + (k * 16) * 1032 + nt * 64 + f * 16,
                                       1032);
                wmma::mma_sync(acc[f], af, bf, acc[f]);
            }
        }
        __syncwarp();
#pragma unroll
        for (int f = 0; f < 4; f++)
            wmma::store_matrix_sync(sCw + f * 16, acc[f], 68, wmma::mem_row_major);
        __syncwarp();
        const float* bp = sBias + nt * 64 + ch * 8;
#pragma unroll
        for (int p = 0; p < 4; p++) {
            int row = p * 4 + rsub;
            const float* rp = sCw + row * 68 + ch * 8;
            float4 v0 = *(const float4*)rp;
            float4 v1 = *(const float4*)(rp + 4);
            __half2 a = __floats2half2_rn(v0.x + bp[0], v0.y + bp[1]);
            __half2 b2 = __floats2half2_rn(v0.z + bp[2], v0.w + bp[3]);
            __half2 c2 = __floats2half2_rn(v1.x + bp[4], v1.y + bp[5]);
            __half2 d2 = __floats2half2_rn(v1.z + bp[6], v1.w + bp[7]);
            int e = blockIdx.x * 128 + wid * 16 + row;
            uint4 pk = make_uint4(*(uint32_t*)&a, *(uint32_t*)&b2,
                                  *(uint32_t*)&c2, *(uint32_t*)&d2);
            st_ef((char*)(void*)g_We + (size_t)e * 2048 + nt * 128 + ch * 16, pk,
                  pol);
        }
        __syncwarp();
    }
}

// ---- msg + scatter, 2 edges per warp (DRAM-bound, ~roofline) ----------------
__global__ __launch_bounds__(256) void msg_kernel(const int* __restrict__ src,
                                                  const int* __restrict__ dst) {
    __shared__ __align__(16) float ns[8][4][32];
    const int w = threadIdx.x >> 5, lane = threadIdx.x & 31;
    const int e0 = blockIdx.x * 16 + w * 2;
    uint64_t pol = mkpol_ef();
    int s0 = __ldg(&src[e0]), s1 = __ldg(&src[e0 + 1]);
    int d0 = __ldg(&dst[e0]), d1 = __ldg(&dst[e0 + 1]);
    ns[w][0][lane] = g_h[(size_t)s0 * 32 + lane];
    ns[w][1][lane] = g_h[N32 + (size_t)s0 * 32 + lane];
    ns[w][2][lane] = g_h[(size_t)s1 * 32 + lane];
    ns[w][3][lane] = g_h[N32 + (size_t)s1 * 32 + lane];
    uint4 q[8];
#pragma unroll
    for (int ee = 0; ee < 2; ee++)
#pragma unroll
        for (int qi = 0; qi < 4; qi++)
            q[ee * 4 + qi] = ld_ef((const char*)(const void*)g_We +
                                       (size_t)(e0 + ee) * 2048 + qi * 512 +
                                       lane * 16,
                                   pol);
    __syncwarp();
    float acc[4] = {0.f, 0.f, 0.f, 0.f};
#pragma unroll
    for (int ee = 0; ee < 2; ee++) {
#pragma unroll
        for (int qi = 0; qi < 4; qi++) {
            uint32_t w4[4] = {q[ee * 4 + qi].x, q[ee * 4 + qi].y,
                              q[ee * 4 + qi].z, q[ee * 4 + qi].w};
#pragma unroll
            for (int u = 0; u < 4; u++) {
                float2 wf = __half22float2(*(__half2*)&w4[u]);
                int h = qi * 8 + 2 * u;
                float2 p0 = *(const float2*)&ns[w][ee * 2][h];
                float2 p1 = *(const float2*)&ns[w][ee * 2 + 1][h];
                acc[ee * 2] += p0.x * wf.x + p0.y * wf.y;
                acc[ee * 2 + 1] += p1.x * wf.x + p1.y * wf.y;
            }
        }
    }
#pragma unroll
    for (int ee = 0; ee < 2; ee++) {
        int d = ee ? d1 : d0;
        float a0 = acc[ee * 2], a1 = acc[ee * 2 + 1];
        float u = __shfl_down_sync(0xffffffffu, a0, 1);
        float v = __shfl_up_sync(0xffffffffu, a1, 1);
        if (!(lane & 1))
            asm volatile("red.global.add.v2.f32 [%0], {%1,%2};"
                         :: "l"(&g_agg[(size_t)d * 32 + lane]), "f"(a0), "f"(u)
                         : "memory");
        else
            asm volatile("red.global.add.v2.f32 [%0], {%1,%2};"
                         :: "l"(&g_agg[N32 + (size_t)d * 32 + lane - 1]), "f"(v),
                            "f"(a1)
                         : "memory");
    }
}

// ---- launch 3 (PROFILED): relu + GRU, 4 nodes per warp-iter x 2 iters -------
__global__ __launch_bounds__(256) void gru_kernel(const float* __restrict__ convb,
                                                  const float* __restrict__ wih,
                                                  const float* __restrict__ whh,
                                                  const float* __restrict__ bih,
                                                  const float* __restrict__ bhh,
                                                  float* __restrict__ outp) {
    __shared__ float sWih[3104], sWhh[3104];  // transposed [h][j], stride 97
    int tid = threadIdx.x, lane = tid & 31;
    for (int i = tid; i < 3072; i += 256) {
        int j = i >> 5, h = i & 31;
        sWih[h * 97 + j] = wih[i];
        sWhh[h * 97 + j] = whh[i];
    }
    float cb = convb[lane];
    float br = bih[lane], bz = bih[32 + lane], bn = bih[64 + lane];
    float cr = bhh[lane], cz = bhh[32 + lane], cn = bhh[64 + lane];
    __syncthreads();
    int w = blockIdx.x * 8 + (tid >> 5);
#pragma unroll 1
    for (int it = 0; it < 2; it++) {
        float nodev[4], hidv[4];
#pragma unroll
        for (int k2 = 0; k2 < 4; k2++) {
            size_t idx = (size_t)(w + (it * 4 + k2) * NW) * 32 + lane;
            nodev[k2] = fmaxf(g_agg[idx] + cb, 0.f);
            g_agg[idx] = 0.f;
            hidv[k2] = g_h[idx];
        }
        float gx0[4], gx1[4], gx2[4], gh0[4], gh1[4], gh2[4];
#pragma unroll
        for (int k2 = 0; k2 < 4; k2++) {
            gx0[k2] = br; gx1[k2] = bz; gx2[k2] = bn;
            gh0[k2] = cr; gh1[k2] = cz; gh2[k2] = cn;
        }
#pragma unroll
        for (int h = 0; h < 32; h++) {
            float wr = sWih[h * 97 + lane];
            float wz = sWih[h * 97 + 32 + lane];
            float wn = sWih[h * 97 + 64 + lane];
            float vr = sWhh[h * 97 + lane];
            float vz = sWhh[h * 97 + 32 + lane];
            float vn = sWhh[h * 97 + 64 + lane];
#pragma unroll
            for (int k2 = 0; k2 < 4; k2++) {
                float nv = __shfl_sync(0xffffffffu, nodev[k2], h);
                float hv = __shfl_sync(0xffffffffu, hidv[k2], h);
                gx0[k2] = fmaf(nv, wr, gx0[k2]);
                gx1[k2] = fmaf(nv, wz, gx1[k2]);
                gx2[k2] = fmaf(nv, wn, gx2[k2]);
                gh0[k2] = fmaf(hv, vr, gh0[k2]);
                gh1[k2] = fmaf(hv, vz, gh1[k2]);
                gh2[k2] = fmaf(hv, vn, gh2[k2]);
            }
        }
#pragma unroll
        for (int k2 = 0; k2 < 4; k2++) {
            float r = fsig(gx0[k2] + gh0[k2]);
            float z = fsig(gx1[k2] + gh1[k2]);
            float n = ftanh(gx2[k2] + r * gh2[k2]);
            float hn = (1.f - z) * n + z * hidv[k2];
            size_t idx = (size_t)(w + (it * 4 + k2) * NW) * 32 + lane;
            g_h[idx] = hn;
            if (outp) outp[idx] = hn;
        }
    }
}

// ------------------------- launch -------------------------------------------
extern "C" void kernel_launch(void* const* d_in, const int* in_sizes, int n_in,
                              void* d_out, int out_size) {
    const float* x     = (const float*)d_in[0];
    const float* rel   = (const float*)d_in[1];
    const float* pw1   = (const float*)d_in[2];
    const float* pb1   = (const float*)d_in[3];
    const float* pw2   = (const float*)d_in[4];
    const float* pb2   = (const float*)d_in[5];
    const float* ew1   = (const float*)d_in[6];
    const float* eb1   = (const float*)d_in[7];
    const float* ew2   = (const float*)d_in[8];
    const float* eb2   = (const float*)d_in[9];
    const float* convb = (const float*)d_in[10];
    const float* wih   = (const float*)d_in[11];
    const float* whh   = (const float*)d_in[12];
    const float* bih   = (const float*)d_in[13];
    const float* bhh   = (const float*)d_in[14];
    const int*   src   = (const int*)d_in[15];
    const int*   dst   = (const int*)d_in[16];
    float* out = (float*)d_out;

    cudaFuncSetAttribute(we_wmma_kernel,
                         cudaFuncAttributeMaxDynamicSharedMemorySize, STOT);
    pre_kernel<<<129 + 27648 + 1728, 256>>>(ew2, eb2, (const float4*)rel, ew1,
                                            eb1, x, pw1, pb1, pw2, pb2);
    we_wmma_kernel<<<NEDGES / 128, 256, STOT>>>();
    for (int step = 0; step < 3; step++) {
        msg_kernel<<<NEDGES / 16, 256>>>(src, dst);
        gru_kernel<<<1728, 256>>>(convb, wih, whh, bih, bhh,
                                  step == 2 ? out : nullptr);
    }
}

// round 11
// speedup vs baseline: 1.4076x; 1.1106x over previous
#include <cuda_runtime.h>
#include <cuda_fp16.h>
#include <mma.h>
#include <cstdint>
#include <cstddef>
using namespace nvcuda;

#define NNODES 55296
#define NEDGES 221184
#define N32 (NNODES * 32)
#define NW 13824  // warps in pre/h0 node pass (1728 blocks x 8)

// ------------------------- device scratch -----------------------------------
__device__ __align__(256) float g_h[2 * N32];
__device__ __align__(256) float g_agg[2 * N32];
__device__ __align__(256) __half g_tA[(size_t)NEDGES * 32];   // t hi fp16
__device__ __align__(256) __half g_Bt[32 * 1024];             // B' permuted
__device__ __align__(256) float g_biasp[1024];                // eb2 permuted
__device__ __align__(256) __half g_We[(size_t)NEDGES * 1024]; // [e][j] j=(q,o,hl)

__device__ __forceinline__ float frcp(float x) {
    float r;
    asm("rcp.approx.f32 %0, %1;" : "=f"(r) : "f"(x));
    return r;
}
__device__ __forceinline__ float fsig(float x) { return frcp(1.f + __expf(-x)); }
__device__ __forceinline__ float ftanh(float x) {
    return 1.f - 2.f * frcp(1.f + __expf(2.f * x));
}
__device__ __forceinline__ uint64_t mkpol_ef() {
    uint64_t p;
    asm("createpolicy.fractional.L2::evict_first.b64 %0;" : "=l"(p));
    return p;
}
__device__ __forceinline__ uint4 ld_ef(const void* gp, uint64_t pol) {
    uint4 v;
    asm volatile("ld.global.nc.L2::cache_hint.v4.u32 {%0,%1,%2,%3}, [%4], %5;"
                 : "=r"(v.x), "=r"(v.y), "=r"(v.z), "=r"(v.w)
                 : "l"(gp), "l"(pol));
    return v;
}
__device__ __forceinline__ void st_ef(void* gp, uint4 v, uint64_t pol) {
    asm volatile("st.global.L2::cache_hint.v4.b32 [%0], {%1,%2,%3,%4}, %5;"
                 :: "l"(gp), "r"(v.x), "r"(v.y), "r"(v.z), "r"(v.w), "l"(pol)
                 : "memory");
}

// ---- launch 0: fused pre: B' build + bias permute + t build + h0 + zero ----
__global__ __launch_bounds__(256) void pre_kernel(
    const float* __restrict__ ew2, const float* __restrict__ eb2,
    const float4* __restrict__ rel4, const float* __restrict__ ew1,
    const float* __restrict__ eb1, const float* __restrict__ x,
    const float* __restrict__ pw1, const float* __restrict__ pb1,
    const float* __restrict__ pw2, const float* __restrict__ pb2) {
    int b = blockIdx.x, tid = threadIdx.x;
    if (b < 128) {               // B' [32][1024]: col j = q*256+o*8+hl
        int i = b * 256 + tid;
        int k = i >> 10, j = i & 1023;
        int h = ((j >> 8) << 3) + (j & 7), o = (j >> 3) & 31;
        g_Bt[i] = __float2half(ew2[k * 1024 + h * 32 + o]);
    } else if (b == 128) {       // permuted bias
#pragma unroll
        for (int u = 0; u < 4; u++) {
            int j = tid * 4 + u;
            int h = ((j >> 8) << 3) + (j & 7), o = (j >> 3) & 31;
            g_biasp[j] = eb2[h * 32 + o];
        }
    } else if (b < 129 + 27648) {  // t = relu(rel@ew1+eb1) -> fp16
        int g = (b - 129) * 256 + tid;
        int e = g >> 5, k = g & 31;
        float4 r = rel4[e];
        float v = eb1[k] + r.x * ew1[k] + r.y * ew1[32 + k] +
                  r.z * ew1[64 + k] + r.w * ew1[96 + k];
        g_tA[(size_t)e * 32 + k] = __float2half(fmaxf(v, 0.f));
    } else {                     // h0 projection + zero g_agg (8 nodes/warp)
        int hb = b - 129 - 27648;  // 0..1727
        __shared__ float sW1[1024], sW2[1024];
        int lane = tid & 31;
#pragma unroll
        for (int i = 0; i < 8; i++)
            g_agg[hb * 256 + tid + i * 442368] = 0.f;
        for (int i = tid; i < 1024; i += 256) { sW1[i] = pw1[i]; sW2[i] = pw2[i]; }
        __syncthreads();
        int wbase = hb * 8 + (tid >> 5);
#pragma unroll 1
        for (int it = 0; it < 8; it++) {
            int gw = wbase + it * NW;
            float xr = x[(size_t)gw * 32 + lane];
            float t1 = pb1[lane];
#pragma unroll
            for (int h = 0; h < 32; h++)
                t1 = fmaf(__shfl_sync(0xffffffffu, xr, h), sW1[h * 32 + lane], t1);
            t1 = fmaxf(t1, 0.f);
            float o = pb2[lane];
#pragma unroll
            for (int h = 0; h < 32; h++)
                o = fmaf(__shfl_sync(0xffffffffu, t1, h), sW2[h * 32 + lane], o);
            g_h[(size_t)gw * 32 + lane] = o;
        }
    }
}

// ---- launch 1: We GEMM [128x32]@[32x1024] wmma (measured 187us) -------------
#define SA 0                 // 128*40*2  = 10240
#define SB 10240             // 32*1032*2 = 66048
#define SC 76288             // 8*16*68*4 = 34816
#define SBIAS 111104         // 4096
#define STOT 115200

__global__ __launch_bounds__(256, 2) void we_wmma_kernel() {
    extern __shared__ char sm[];
    __half* sA = (__half*)(sm + SA);
    __half* sB = (__half*)(sm + SB);
    float* sC = (float*)(sm + SC);
    float* sBias = (float*)(sm + SBIAS);
    int tid = threadIdx.x, wid = tid >> 5, lane = tid & 31;
    uint64_t pol = mkpol_ef();

    const uint4* ga = (const uint4*)(g_tA + (size_t)blockIdx.x * 128 * 32);
#pragma unroll
    for (int r = 0; r < 2; r++) {
        int i = tid + r * 256, row = i >> 2, c = i & 3;
        *(uint4*)(sA + row * 40 + c * 8) = ga[i];
    }
    const uint4* gb = (const uint4*)(const void*)g_Bt;
#pragma unroll
    for (int r = 0; r < 16; r++) {
        int i = tid + r * 256, row = i >> 7, c = i & 127;
        *(uint4*)(sB + row * 1032 + c * 8) = gb[i];
    }
#pragma unroll
    for (int r = 0; r < 4; r++) sBias[tid + r * 256] = g_biasp[tid + r * 256];
    __syncthreads();

    float* sCw = sC + wid * 16 * 68;
    const int rsub = lane >> 3, ch = lane & 7;
    for (int nt = 0; nt < 16; nt++) {
        wmma::fragment<wmma::accumulator, 16, 16, 16, float> acc[4];
#pragma unroll
        for (int f = 0; f < 4; f++) wmma::fill_fragment(acc[f], 0.f);
#pragma unroll
        for (int k = 0; k < 2; k++) {
            wmma::fragment<wmma::matrix_a, 16, 16, 16, __half, wmma::row_major> af;
            wmma::load_matrix_sync(af, sA + (wid * 16) * 40 + k * 16, 40);
#pragma unroll
            for (int f = 0; f < 4; f++) {
                wmma::fragment<wmma::matrix_b, 16, 16, 16, __half, wmma::row_major> bf;
                wmma::load_matrix_sync(bf, sB + (k * 16) * 1032 + nt * 64 + f * 16,
                                       1032);
                wmma::mma_sync(acc[f], af, bf, acc[f]);
            }
        }
        __syncwarp();
#pragma unroll
        for (int f = 0; f < 4; f++)
            wmma::store_matrix_sync(sCw + f * 16, acc[f], 68, wmma::mem_row_major);
        __syncwarp();
        const float* bp = sBias + nt * 64 + ch * 8;
#pragma unroll
        for (int p = 0; p < 4; p++) {
            int row = p * 4 + rsub;
            const float* rp = sCw + row * 68 + ch * 8;
            float4 v0 = *(const float4*)rp;
            float4 v1 = *(const float4*)(rp + 4);
            __half2 a = __floats2half2_rn(v0.x + bp[0], v0.y + bp[1]);
            __half2 b2 = __floats2half2_rn(v0.z + bp[2], v0.w + bp[3]);
            __half2 c2 = __floats2half2_rn(v1.x + bp[4], v1.y + bp[5]);
            __half2 d2 = __floats2half2_rn(v1.z + bp[6], v1.w + bp[7]);
            int e = blockIdx.x * 128 + wid * 16 + row;
            uint4 pk = make_uint4(*(uint32_t*)&a, *(uint32_t*)&b2,
                                  *(uint32_t*)&c2, *(uint32_t*)&d2);
            st_ef((char*)(void*)g_We + (size_t)e * 2048 + nt * 128 + ch * 16, pk,
                  pol);
        }
        __syncwarp();
    }
}

// ---- msg + scatter, 2 edges per warp (DRAM-bound, ~roofline) ----------------
__global__ __launch_bounds__(256) void msg_kernel(const int* __restrict__ src,
                                                  const int* __restrict__ dst) {
    __shared__ __align__(16) float ns[8][4][32];
    const int w = threadIdx.x >> 5, lane = threadIdx.x & 31;
    const int e0 = blockIdx.x * 16 + w * 2;
    uint64_t pol = mkpol_ef();
    int s0 = __ldg(&src[e0]), s1 = __ldg(&src[e0 + 1]);
    int d0 = __ldg(&dst[e0]), d1 = __ldg(&dst[e0 + 1]);
    ns[w][0][lane] = g_h[(size_t)s0 * 32 + lane];
    ns[w][1][lane] = g_h[N32 + (size_t)s0 * 32 + lane];
    ns[w][2][lane] = g_h[(size_t)s1 * 32 + lane];
    ns[w][3][lane] = g_h[N32 + (size_t)s1 * 32 + lane];
    uint4 q[8];
#pragma unroll
    for (int ee = 0; ee < 2; ee++)
#pragma unroll
        for (int qi = 0; qi < 4; qi++)
            q[ee * 4 + qi] = ld_ef((const char*)(const void*)g_We +
                                       (size_t)(e0 + ee) * 2048 + qi * 512 +
                                       lane * 16,
                                   pol);
    __syncwarp();
    float acc[4] = {0.f, 0.f, 0.f, 0.f};
#pragma unroll
    for (int ee = 0; ee < 2; ee++) {
#pragma unroll
        for (int qi = 0; qi < 4; qi++) {
            uint32_t w4[4] = {q[ee * 4 + qi].x, q[ee * 4 + qi].y,
                              q[ee * 4 + qi].z, q[ee * 4 + qi].w};
#pragma unroll
            for (int u = 0; u < 4; u++) {
                float2 wf = __half22float2(*(__half2*)&w4[u]);
                int h = qi * 8 + 2 * u;
                float2 p0 = *(const float2*)&ns[w][ee * 2][h];
                float2 p1 = *(const float2*)&ns[w][ee * 2 + 1][h];
                acc[ee * 2] += p0.x * wf.x + p0.y * wf.y;
                acc[ee * 2 + 1] += p1.x * wf.x + p1.y * wf.y;
            }
        }
    }
#pragma unroll
    for (int ee = 0; ee < 2; ee++) {
        int d = ee ? d1 : d0;
        float a0 = acc[ee * 2], a1 = acc[ee * 2 + 1];
        float u = __shfl_down_sync(0xffffffffu, a0, 1);
        float v = __shfl_up_sync(0xffffffffu, a1, 1);
        if (!(lane & 1))
            asm volatile("red.global.add.v2.f32 [%0], {%1,%2};"
                         :: "l"(&g_agg[(size_t)d * 32 + lane]), "f"(a0), "f"(u)
                         : "memory");
        else
            asm volatile("red.global.add.v2.f32 [%0], {%1,%2};"
                         :: "l"(&g_agg[N32 + (size_t)d * 32 + lane - 1]), "f"(v),
                            "f"(a1)
                         : "memory");
    }
}

// ---- launch 3 (PROFILED): tensor-core GRU -----------------------------------
// block = 128 nodes; gx = [node_hi|node_lo] @ [Wih^T;Wih^T]  (K=64), same for gh
#define GV 0                 // 128*72*2 = 18432  node hi/lo fp16
#define GH 18432             // 18432            hidden hi/lo fp16
#define GWX 36864            // 64*104*2 = 13312 Wih' dup rows
#define GWH 50176            // 13312            Whh'
#define GGX 63488            // 128*100*4 = 51200
#define GGH 114688           // 51200
#define GBIA 165888          // 192*4 = 768
#define GTOT 166656

__global__ __launch_bounds__(256) void gru_kernel(const float* __restrict__ convb,
                                                  const float* __restrict__ wih,
                                                  const float* __restrict__ whh,
                                                  const float* __restrict__ bih,
                                                  const float* __restrict__ bhh,
                                                  float* __restrict__ outp) {
    extern __shared__ char sm[];
    __half* sV = (__half*)(sm + GV);
    __half* sH = (__half*)(sm + GH);
    __half* sWx = (__half*)(sm + GWX);
    __half* sWh = (__half*)(sm + GWH);
    float* sGX = (float*)(sm + GGX);
    float* sGH = (float*)(sm + GGH);
    float* sB = (float*)(sm + GBIA);
    int tid = threadIdx.x, wid = tid >> 5;
    size_t base = (size_t)blockIdx.x * 4096;

    // stage values (relu+hi/lo), hidden (hi/lo); reset agg
#pragma unroll
    for (int i = 0; i < 16; i++) {
        int v = tid + i * 256, row = v >> 5, col = v & 31;
        float nf = fmaxf(g_agg[base + v] + convb[col], 0.f);
        g_agg[base + v] = 0.f;
        __half nh = __float2half(nf);
        sV[row * 72 + col] = nh;
        sV[row * 72 + 32 + col] = __float2half(nf - __half2float(nh));
        float hf = g_h[base + v];
        __half hh = __float2half(hf);
        sH[row * 72 + col] = hh;
        sH[row * 72 + 32 + col] = __float2half(hf - __half2float(hh));
    }
    // weights transposed + row-duplicated: sW[k][j] = w[j*32+k], k and k+32
#pragma unroll
    for (int i = 0; i < 12; i++) {
        int v = tid + i * 256, j = v >> 5, k = v & 31;
        __half a = __float2half(wih[v]);
        sWx[k * 104 + j] = a;
        sWx[(k + 32) * 104 + j] = a;
        __half b = __float2half(whh[v]);
        sWh[k * 104 + j] = b;
        sWh[(k + 32) * 104 + j] = b;
    }
    if (tid < 96) { sB[tid] = bih[tid]; sB[96 + tid] = bhh[tid]; }
    __syncthreads();

    // two GEMMs: [128x64]@[64x96] -> fp32 smem
    {
        wmma::fragment<wmma::accumulator, 16, 16, 16, float> acc[6];
        const __half* sAax[2] = {sV, sH};
        const __half* sWax[2] = {sWx, sWh};
        float* sGax[2] = {sGX, sGH};
#pragma unroll 1
        for (int g = 0; g < 2; g++) {
#pragma unroll
            for (int f = 0; f < 6; f++) wmma::fill_fragment(acc[f], 0.f);
#pragma unroll
            for (int k = 0; k < 4; k++) {
                wmma::fragment<wmma::matrix_a, 16, 16, 16, __half, wmma::row_major> af;
                wmma::load_matrix_sync(af, sAax[g] + (wid * 16) * 72 + k * 16, 72);
#pragma unroll
                for (int f = 0; f < 6; f++) {
                    wmma::fragment<wmma::matrix_b, 16, 16, 16, __half,
                                   wmma::row_major> bf;
                    wmma::load_matrix_sync(bf, sWax[g] + (k * 16) * 104 + f * 16,
                                           104);
                    wmma::mma_sync(acc[f], af, bf, acc[f]);
                }
            }
#pragma unroll
            for (int f = 0; f < 6; f++)
                wmma::store_matrix_sync(sGax[g] + (wid * 16) * 100 + f * 16, acc[f],
                                        100, wmma::mem_row_major);
        }
    }
    __syncthreads();

    // elementwise gates + state update
#pragma unroll
    for (int i = 0; i < 16; i++) {
        int v = tid + i * 256, row = v >> 5, j = v & 31;
        const float* gx = sGX + row * 100;
        const float* gh = sGH + row * 100;
        float r = fsig(gx[j] + gh[j] + sB[j] + sB[96 + j]);
        float z = fsig(gx[32 + j] + gh[32 + j] + sB[32 + j] + sB[128 + j]);
        float n = ftanh(gx[64 + j] + sB[64 + j] + r * (gh[64 + j] + sB[160 + j]));
        float hid = g_h[base + v];
        float hn = (1.f - z) * n + z * hid;
        g_h[base + v] = hn;
        if (outp) outp[base + v] = hn;
    }
}

// ------------------------- launch -------------------------------------------
extern "C" void kernel_launch(void* const* d_in, const int* in_sizes, int n_in,
                              void* d_out, int out_size) {
    const float* x     = (const float*)d_in[0];
    const float* rel   = (const float*)d_in[1];
    const float* pw1   = (const float*)d_in[2];
    const float* pb1   = (const float*)d_in[3];
    const float* pw2   = (const float*)d_in[4];
    const float* pb2   = (const float*)d_in[5];
    const float* ew1   = (const float*)d_in[6];
    const float* eb1   = (const float*)d_in[7];
    const float* ew2   = (const float*)d_in[8];
    const float* eb2   = (const float*)d_in[9];
    const float* convb = (const float*)d_in[10];
    const float* wih   = (const float*)d_in[11];
    const float* whh   = (const float*)d_in[12];
    const float* bih   = (const float*)d_in[13];
    const float* bhh   = (const float*)d_in[14];
    const int*   src   = (const int*)d_in[15];
    const int*   dst   = (const int*)d_in[16];
    float* out = (float*)d_out;

    cudaFuncSetAttribute(we_wmma_kernel,
                         cudaFuncAttributeMaxDynamicSharedMemorySize, STOT);
    cudaFuncSetAttribute(gru_kernel,
                         cudaFuncAttributeMaxDynamicSharedMemorySize, GTOT);
    pre_kernel<<<129 + 27648 + 1728, 256>>>(ew2, eb2, (const float4*)rel, ew1,
                                            eb1, x, pw1, pb1, pw2, pb2);
    we_wmma_kernel<<<NEDGES / 128, 256, STOT>>>();
    for (int step = 0; step < 3; step++) {
        msg_kernel<<<NEDGES / 16, 256>>>(src, dst);
        gru_kernel<<<864, 256, GTOT>>>(convb, wih, whh, bih, bhh,
                                       step == 2 ? out : nullptr);
    }
}